// round 3
// baseline (speedup 1.0000x reference)
#include <cuda_runtime.h>
#include <cuda_bf16.h>
#include <math.h>

// ---------------------------------------------------------------------------
// OwlViT prediction head
//   B=32, P=576, DV=768, DT=512, N_PARTS=12, K=3, NUM_CLASSES=800
//   out = [logits_reshaped (384*9600) | pred_logits (32*800)] fp32
// ---------------------------------------------------------------------------

#define Bsz 32
#define Pn 576
#define DV 768
#define DT 512
#define NPART 12
#define TOPK 3
#define NCLS 800
#define NQ (NCLS * NPART)      // 9600 query rows per batch
#define MROWS (Bsz * NPART)    // 384
#define LOGITS_ELEMS ((size_t)MROWS * NQ)

// scratch (static device memory; no allocations allowed)
__device__ float g_parts[MROWS * DV];
__device__ float g_h1[MROWS * DV];
__device__ float g_h2[MROWS * DV];
__device__ float g_img[MROWS * DT];

// ---------------------------------------------------------------------------
// packed f32x2 FMA (sm_100+)
// ---------------------------------------------------------------------------
__device__ __forceinline__ void fma2(unsigned long long& d,
                                     unsigned long long a,
                                     unsigned long long b) {
    asm("fma.rn.f32x2 %0, %1, %2, %0;" : "+l"(d) : "l"(a), "l"(b));
}

__device__ __forceinline__ float pair_sum(unsigned long long v) {
    float lo = __uint_as_float((unsigned)(v & 0xffffffffull));
    float hi = __uint_as_float((unsigned)(v >> 32));
    return lo + hi;
}

__device__ __forceinline__ float gelu_exact(float x) {
    return 0.5f * x * (1.0f + erff(x * 0.70710678118654752f));
}

// ---------------------------------------------------------------------------
// 1) gather + dedup:  parts[row] = sum over unique topk patches
//    topk_idxs layout: [B, K, NPART] int32 (JAX x64 disabled -> int32)
// ---------------------------------------------------------------------------
__global__ void gather_kernel(const float* __restrict__ img_e,
                              const int* __restrict__ idx) {
    int row = blockIdx.x;            // 0..383
    int b = row / NPART, n = row % NPART;
    int i0 = idx[(b * TOPK + 0) * NPART + n];
    int i1 = idx[(b * TOPK + 1) * NPART + n];
    int i2 = idx[(b * TOPK + 2) * NPART + n];
    // defensive clamp (turns a wrong-dtype bug into rel_err, not a fault)
    i0 = min(max(i0, 0), Pn - 1);
    i1 = min(max(i1, 0), Pn - 1);
    i2 = min(max(i2, 0), Pn - 1);
    bool u1 = (i1 != i0);
    bool u2 = (i2 != i0) && (i2 != i1);
    const float* base = img_e + (size_t)b * Pn * DV;
    int d = threadIdx.x * 4;         // blockDim = 192 -> covers 768
    float4 s = *(const float4*)(base + (size_t)i0 * DV + d);
    if (u1) {
        float4 v = *(const float4*)(base + (size_t)i1 * DV + d);
        s.x += v.x; s.y += v.y; s.z += v.z; s.w += v.w;
    }
    if (u2) {
        float4 v = *(const float4*)(base + (size_t)i2 * DV + d);
        s.x += v.x; s.y += v.y; s.z += v.z; s.w += v.w;
    }
    *(float4*)(g_parts + (size_t)row * DV + d) = s;
}

// ---------------------------------------------------------------------------
// 2) tiled SGEMM:  C[M,N] = gelu(A[M,768] * W[N,768]^T + bias)
//    BM=64 BN=64 BK=16, 256 threads, 4x4 per thread
// ---------------------------------------------------------------------------
#define GBM 64
#define GBN 64
#define GBK 16
__global__ void __launch_bounds__(256)
gemm_bias_gelu(const float* __restrict__ A, const float* __restrict__ W,
               const float* __restrict__ bias, float* __restrict__ C, int N) {
    __shared__ __align__(16) float As[GBK][GBM];
    __shared__ __align__(16) float Ws[GBK][GBN];
    int tx = threadIdx.x & 15;
    int ty = threadIdx.x >> 4;
    int bm = blockIdx.x * GBM;
    int bn = blockIdx.y * GBN;

    int lrow = threadIdx.x >> 2;          // 0..63
    int lk4  = (threadIdx.x & 3) << 2;    // 0,4,8,12

    float acc[4][4] = {};

    for (int k0 = 0; k0 < DV; k0 += GBK) {
        float4 av = *(const float4*)(A + (size_t)(bm + lrow) * DV + k0 + lk4);
        float4 wv = *(const float4*)(W + (size_t)(bn + lrow) * DV + k0 + lk4);
        __syncthreads();
        As[lk4 + 0][lrow] = av.x; As[lk4 + 1][lrow] = av.y;
        As[lk4 + 2][lrow] = av.z; As[lk4 + 3][lrow] = av.w;
        Ws[lk4 + 0][lrow] = wv.x; Ws[lk4 + 1][lrow] = wv.y;
        Ws[lk4 + 2][lrow] = wv.z; Ws[lk4 + 3][lrow] = wv.w;
        __syncthreads();
#pragma unroll
        for (int k = 0; k < GBK; ++k) {
            float4 a = *(const float4*)&As[k][ty * 4];
            float4 w = *(const float4*)&Ws[k][tx * 4];
            float av4[4] = {a.x, a.y, a.z, a.w};
            float wv4[4] = {w.x, w.y, w.z, w.w};
#pragma unroll
            for (int i = 0; i < 4; ++i)
#pragma unroll
                for (int j = 0; j < 4; ++j)
                    acc[i][j] = fmaf(av4[i], wv4[j], acc[i][j]);
        }
    }
#pragma unroll
    for (int i = 0; i < 4; ++i) {
        int row = bm + ty * 4 + i;
#pragma unroll
        for (int j = 0; j < 4; ++j) {
            int col = bn + tx * 4 + j;
            float x = acc[i][j] + bias[col];
            C[(size_t)row * N + col] = gelu_exact(x);
        }
    }
}

// ---------------------------------------------------------------------------
// 3) row-wise L2 normalization of img [384, 512] (in place)
// ---------------------------------------------------------------------------
__global__ void l2norm_kernel() {
    __shared__ float red[4];
    int row = blockIdx.x;
    int t = threadIdx.x;                 // 128 threads
    float4 v = *(float4*)(g_img + (size_t)row * DT + t * 4);
    float ss = v.x * v.x + v.y * v.y + v.z * v.z + v.w * v.w;
#pragma unroll
    for (int off = 16; off > 0; off >>= 1)
        ss += __shfl_xor_sync(0xffffffffu, ss, off);
    if ((t & 31) == 0) red[t >> 5] = ss;
    __syncthreads();
    float tot = red[0] + red[1] + red[2] + red[3];
    float rinv = 1.0f / fmaxf(sqrtf(tot), 1e-12f);
    v.x *= rinv; v.y *= rinv; v.z *= rinv; v.w *= rinv;
    *(float4*)(g_img + (size_t)row * DT + t * 4) = v;
}

// ---------------------------------------------------------------------------
// 4) hot kernel: logits[b,n,i] = dot(img_n[b,n], q[b,i]) / max(||q[b,i]||, eps)
//    384 threads (12 warps), each warp: 4 q-rows, 13 f32x2 accumulators.
//    grid = (100, 32); each block handles 96 consecutive q-rows of one batch.
// ---------------------------------------------------------------------------
__global__ void __launch_bounds__(384, 1)
logits_kernel(const float* __restrict__ q, float* __restrict__ out) {
    __shared__ __align__(16) float img_s[NPART * DT];   // 24 KB
    int b = blockIdx.y;

    // stage normalized img tile for this batch
    {
        const float4* src = (const float4*)(g_img + (size_t)b * NPART * DT);
        float4* dst = (float4*)img_s;
        for (int t = threadIdx.x; t < NPART * DT / 4; t += 384) dst[t] = src[t];
    }
    __syncthreads();

    int warp = threadIdx.x >> 5;
    int lane = threadIdx.x & 31;
    const float* qb = q + (size_t)b * NQ * DT;

#pragma unroll 1
    for (int p = 0; p < 2; ++p) {
        int r0 = blockIdx.x * 96 + p * 48 + warp * 4;

        unsigned long long acc[4][13];
#pragma unroll
        for (int r = 0; r < 4; ++r)
#pragma unroll
            for (int j = 0; j < 13; ++j) acc[r][j] = 0ull;

#pragma unroll
        for (int it = 0; it < 4; ++it) {
            int k = it * 128 + lane * 4;
            ulonglong2 qv[4];
#pragma unroll
            for (int r = 0; r < 4; ++r)
                qv[r] = *(const ulonglong2*)(qb + (size_t)(r0 + r) * DT + k);
#pragma unroll
            for (int n = 0; n < NPART; ++n) {
                ulonglong2 im = *(const ulonglong2*)(&img_s[n * DT + k]);
#pragma unroll
                for (int r = 0; r < 4; ++r) {
                    fma2(acc[r][n], qv[r].x, im.x);
                    fma2(acc[r][n], qv[r].y, im.y);
                }
            }
#pragma unroll
            for (int r = 0; r < 4; ++r) {
                fma2(acc[r][12], qv[r].x, qv[r].x);
                fma2(acc[r][12], qv[r].y, qv[r].y);
            }
        }

#pragma unroll
        for (int r = 0; r < 4; ++r) {
            float s[13];
#pragma unroll
            for (int j = 0; j < 13; ++j) s[j] = pair_sum(acc[r][j]);
#pragma unroll
            for (int j = 0; j < 13; ++j) {
#pragma unroll
                for (int off = 16; off > 0; off >>= 1)
                    s[j] += __shfl_xor_sync(0xffffffffu, s[j], off);
            }
            float rinv = 1.0f / fmaxf(sqrtf(s[12]), 1e-12f);
            int i = r0 + r;
            if (lane < NPART)
                out[((size_t)(b * NPART + lane)) * NQ + i] = s[lane] * rinv;
        }
    }
}

// ---------------------------------------------------------------------------
// 5) pred_logits[b,c] = sum_n logits[b,n,c*12+n]
// ---------------------------------------------------------------------------
__global__ void pred_kernel(float* __restrict__ out) {
    int t = blockIdx.x * blockDim.x + threadIdx.x;   // 0..25599
    if (t >= Bsz * NCLS) return;
    int b = t / NCLS, c = t % NCLS;
    float s = 0.0f;
#pragma unroll
    for (int n = 0; n < NPART; ++n)
        s += out[((size_t)(b * NPART + n)) * NQ + c * NPART + n];
    out[LOGITS_ELEMS + t] = s;
}

// ---------------------------------------------------------------------------
extern "C" void kernel_launch(void* const* d_in, const int* in_sizes, int n_in,
                              void* d_out, int out_size) {
    const float* image = (const float*)d_in[0];
    const float* query = (const float*)d_in[1];
    const int* topk = (const int*)d_in[2];
    const float* W1 = (const float*)d_in[3];
    const float* b1 = (const float*)d_in[4];
    const float* W2 = (const float*)d_in[5];
    const float* b2 = (const float*)d_in[6];
    const float* W3 = (const float*)d_in[7];
    const float* b3 = (const float*)d_in[8];
    float* out = (float*)d_out;

    float* parts; float* h1; float* h2; float* img;
    cudaGetSymbolAddress((void**)&parts, g_parts);
    cudaGetSymbolAddress((void**)&h1, g_h1);
    cudaGetSymbolAddress((void**)&h2, g_h2);
    cudaGetSymbolAddress((void**)&img, g_img);

    gather_kernel<<<MROWS, 192>>>(image, topk);
    gemm_bias_gelu<<<dim3(MROWS / GBM, DV / GBN), 256>>>(parts, W1, b1, h1, DV);
    gemm_bias_gelu<<<dim3(MROWS / GBM, DV / GBN), 256>>>(h1, W2, b2, h2, DV);
    gemm_bias_gelu<<<dim3(MROWS / GBM, DT / GBN), 256>>>(h2, W3, b3, img, DT);
    l2norm_kernel<<<MROWS, 128>>>();
    logits_kernel<<<dim3(NQ / 96, Bsz), 384>>>(query, out);
    pred_kernel<<<(Bsz * NCLS + 255) / 256, 256>>>(out);
}

// round 4
// speedup vs baseline: 1.4684x; 1.4684x over previous
#include <cuda_runtime.h>
#include <cuda_bf16.h>
#include <math.h>

// ---------------------------------------------------------------------------
// OwlViT prediction head
//   B=32, P=576, DV=768, DT=512, N_PARTS=12, K=3, NUM_CLASSES=800
//   out = [logits_reshaped (384*9600) | pred_logits (32*800)] fp32
// ---------------------------------------------------------------------------

#define Bsz 32
#define Pn 576
#define DV 768
#define DT 512
#define NPART 12
#define TOPK 3
#define NCLS 800
#define NQ (NCLS * NPART)      // 9600 query rows per batch
#define MROWS (Bsz * NPART)    // 384
#define LOGITS_ELEMS ((size_t)MROWS * NQ)

// scratch (static device memory; no allocations allowed)
__device__ float g_parts[MROWS * DV];
__device__ float g_h1[MROWS * DV];
__device__ float g_h2[MROWS * DV];
__device__ float g_img[MROWS * DT];

// ---------------------------------------------------------------------------
// packed f32x2 FMA (sm_100+)
// ---------------------------------------------------------------------------
__device__ __forceinline__ void fma2(unsigned long long& d,
                                     unsigned long long a,
                                     unsigned long long b) {
    asm("fma.rn.f32x2 %0, %1, %2, %0;" : "+l"(d) : "l"(a), "l"(b));
}

__device__ __forceinline__ float pair_sum(unsigned long long v) {
    float lo = __uint_as_float((unsigned)(v & 0xffffffffull));
    float hi = __uint_as_float((unsigned)(v >> 32));
    return lo + hi;
}

__device__ __forceinline__ float gelu_exact(float x) {
    return 0.5f * x * (1.0f + erff(x * 0.70710678118654752f));
}

// ---------------------------------------------------------------------------
// 1) gather + dedup:  parts[row] = sum over unique topk patches
//    topk_idxs layout: [B, K, NPART] int32
// ---------------------------------------------------------------------------
__global__ void gather_kernel(const float* __restrict__ img_e,
                              const int* __restrict__ idx) {
    int row = blockIdx.x;            // 0..383
    int b = row / NPART, n = row % NPART;
    int i0 = idx[(b * TOPK + 0) * NPART + n];
    int i1 = idx[(b * TOPK + 1) * NPART + n];
    int i2 = idx[(b * TOPK + 2) * NPART + n];
    i0 = min(max(i0, 0), Pn - 1);
    i1 = min(max(i1, 0), Pn - 1);
    i2 = min(max(i2, 0), Pn - 1);
    bool u1 = (i1 != i0);
    bool u2 = (i2 != i0) && (i2 != i1);
    const float* base = img_e + (size_t)b * Pn * DV;
    int d = threadIdx.x * 4;         // blockDim = 192 -> covers 768
    float4 s = *(const float4*)(base + (size_t)i0 * DV + d);
    if (u1) {
        float4 v = *(const float4*)(base + (size_t)i1 * DV + d);
        s.x += v.x; s.y += v.y; s.z += v.z; s.w += v.w;
    }
    if (u2) {
        float4 v = *(const float4*)(base + (size_t)i2 * DV + d);
        s.x += v.x; s.y += v.y; s.z += v.z; s.w += v.w;
    }
    *(float4*)(g_parts + (size_t)row * DV + d) = s;
}

// ---------------------------------------------------------------------------
// 2) tiled SGEMM:  C[M,N] = gelu(A[M,768] * W[N,768]^T + bias)
//    BM=32 BN=64 BK=32, 256 threads, 2x4 outputs/thread, f32x2 k-pair FMAs.
//    smem stored k-major with pad 36; n-mapping tx+16j -> conflict-free LDS.
// ---------------------------------------------------------------------------
#define GBM 32
#define GBN 64
#define GBK 32
#define GPAD 36
__global__ void __launch_bounds__(256)
gemm_bias_gelu(const float* __restrict__ A, const float* __restrict__ W,
               const float* __restrict__ bias, float* __restrict__ C, int N) {
    __shared__ __align__(16) float As[GBM][GPAD];
    __shared__ __align__(16) float Ws[GBN][GPAD];
    int t = threadIdx.x;
    int tx = t & 15;                 // n-lane: cols tx + 16j
    int ty = t >> 4;                 // 0..15 : rows ty*2 + i
    int bm = blockIdx.x * GBM, bn = blockIdx.y * GBN;

    int ar = t >> 3, ak = (t & 7) * 4;    // A tile: 32 rows x 32 k, 1 float4/thread
    int wr = t >> 2, wk = (t & 3) * 8;    // W tile: 64 rows x 32 k, 2 float4/thread
    const float* Ag = A + (size_t)(bm + ar) * DV + ak;
    const float* Wg = W + (size_t)(bn + wr) * DV + wk;

    unsigned long long acc2[2][4];
#pragma unroll
    for (int i = 0; i < 2; ++i)
#pragma unroll
        for (int j = 0; j < 4; ++j) acc2[i][j] = 0ull;

    float4 a0 = *(const float4*)Ag;
    float4 w0 = *(const float4*)Wg;
    float4 w1 = *(const float4*)(Wg + 4);

    for (int k0 = 0; k0 < DV; k0 += GBK) {
        __syncthreads();
        *(float4*)&As[ar][ak] = a0;
        *(float4*)&Ws[wr][wk] = w0;
        *(float4*)&Ws[wr][wk + 4] = w1;
        __syncthreads();
        if (k0 + GBK < DV) {
            a0 = *(const float4*)(Ag + k0 + GBK);
            w0 = *(const float4*)(Wg + k0 + GBK);
            w1 = *(const float4*)(Wg + k0 + GBK + 4);
        }
#pragma unroll
        for (int kk = 0; kk < GBK; kk += 4) {     // 2 k-pairs per step
            ulonglong2 ap[2];
#pragma unroll
            for (int i = 0; i < 2; ++i)
                ap[i] = *(const ulonglong2*)&As[ty * 2 + i][kk];
            ulonglong2 wp[4];
#pragma unroll
            for (int j = 0; j < 4; ++j)
                wp[j] = *(const ulonglong2*)&Ws[tx + 16 * j][kk];
#pragma unroll
            for (int i = 0; i < 2; ++i)
#pragma unroll
                for (int j = 0; j < 4; ++j) {
                    fma2(acc2[i][j], ap[i].x, wp[j].x);
                    fma2(acc2[i][j], ap[i].y, wp[j].y);
                }
        }
    }

#pragma unroll
    for (int i = 0; i < 2; ++i) {
        int row = bm + ty * 2 + i;
#pragma unroll
        for (int j = 0; j < 4; ++j) {
            int col = bn + tx + 16 * j;
            float x = pair_sum(acc2[i][j]) + bias[col];
            C[(size_t)row * N + col] = gelu_exact(x);
        }
    }
}

// ---------------------------------------------------------------------------
// 3) row-wise L2 normalization of img [384, 512] (in place)
// ---------------------------------------------------------------------------
__global__ void l2norm_kernel() {
    __shared__ float red[4];
    int row = blockIdx.x;
    int t = threadIdx.x;                 // 128 threads
    float4 v = *(float4*)(g_img + (size_t)row * DT + t * 4);
    float ss = v.x * v.x + v.y * v.y + v.z * v.z + v.w * v.w;
#pragma unroll
    for (int off = 16; off > 0; off >>= 1)
        ss += __shfl_xor_sync(0xffffffffu, ss, off);
    if ((t & 31) == 0) red[t >> 5] = ss;
    __syncthreads();
    float tot = red[0] + red[1] + red[2] + red[3];
    float rinv = 1.0f / fmaxf(sqrtf(tot), 1e-12f);
    v.x *= rinv; v.y *= rinv; v.z *= rinv; v.w *= rinv;
    *(float4*)(g_img + (size_t)row * DT + t * 4) = v;
}

// ---------------------------------------------------------------------------
// 4) hot kernel: logits[b,n,i] = dot(img_n[b,n], q[b,i]) / max(||q[b,i]||,eps)
//    256 threads (8 warps), 2 q-rows/warp, 6 passes -> 96 rows/block.
//    All 8 LDG.128 per pass issued up front (MLP). f32x2 accumulate.
//    Lane-specialized tree reduction: 16 values (13 real), 16 shfl/row.
// ---------------------------------------------------------------------------
__global__ void __launch_bounds__(256, 2)
logits_kernel(const float* __restrict__ q, float* __restrict__ out) {
    __shared__ __align__(16) float img_s[NPART * DT];   // 24 KB
    int b = blockIdx.y;

    {   // stage normalized img tile for this batch (1536 float4, 6/thread)
        const float4* src = (const float4*)(g_img + (size_t)b * NPART * DT);
        float4* dst = (float4*)img_s;
#pragma unroll
        for (int i = 0; i < 6; ++i) dst[threadIdx.x + i * 256] = src[threadIdx.x + i * 256];
    }
    __syncthreads();

    int warp = threadIdx.x >> 5;
    int lane = threadIdx.x & 31;
    const float* qb = q + (size_t)b * NQ * DT;
    int rowbase = blockIdx.x * 96 + warp * 2;

#pragma unroll 1
    for (int p = 0; p < 6; ++p) {
        int r0 = rowbase + p * 16;

        // batched global loads: 2 rows x 4 x LDG.128
        ulonglong2 qv[2][4];
#pragma unroll
        for (int r = 0; r < 2; ++r) {
            const float* qr = qb + (size_t)(r0 + r) * DT + lane * 4;
#pragma unroll
            for (int it = 0; it < 4; ++it)
                qv[r][it] = *(const ulonglong2*)(qr + it * 128);
        }

        unsigned long long acc[2][13];
#pragma unroll
        for (int r = 0; r < 2; ++r)
#pragma unroll
            for (int j = 0; j < 13; ++j) acc[r][j] = 0ull;

#pragma unroll
        for (int it = 0; it < 4; ++it) {
            int k = it * 128 + lane * 4;
#pragma unroll
            for (int n = 0; n < NPART; ++n) {
                ulonglong2 im = *(const ulonglong2*)&img_s[n * DT + k];
                fma2(acc[0][n], qv[0][it].x, im.x);
                fma2(acc[0][n], qv[0][it].y, im.y);
                fma2(acc[1][n], qv[1][it].x, im.x);
                fma2(acc[1][n], qv[1][it].y, im.y);
            }
            fma2(acc[0][12], qv[0][it].x, qv[0][it].x);
            fma2(acc[0][12], qv[0][it].y, qv[0][it].y);
            fma2(acc[1][12], qv[1][it].x, qv[1][it].x);
            fma2(acc[1][12], qv[1][it].y, qv[1][it].y);
        }

#pragma unroll
        for (int r = 0; r < 2; ++r) {
            float v[16];
#pragma unroll
            for (int j = 0; j < 13; ++j) v[j] = pair_sum(acc[r][j]);
            v[13] = 0.0f; v[14] = 0.0f; v[15] = 0.0f;

            // halving tree: after this, lanes {2j,2j+1} hold value j=(lane>>1)&15
#pragma unroll
            for (int d = 16; d >= 2; d >>= 1) {
#pragma unroll
                for (int j = 0; j < d / 2; ++j) {
                    float send = (lane & d) ? v[j] : v[j + d / 2];
                    float recv = __shfl_xor_sync(0xffffffffu, send, d);
                    v[j] = (lane & d) ? (v[j + d / 2] + recv) : (v[j] + recv);
                }
            }
            v[0] += __shfl_xor_sync(0xffffffffu, v[0], 1);

            int idx = (lane >> 1) & 15;
            float nq = __shfl_sync(0xffffffffu, v[0], 24);   // value 12 = |q|^2
            float rinv = 1.0f / fmaxf(sqrtf(nq), 1e-12f);
            if (((lane & 1) == 0) && idx < NPART)
                out[((size_t)(b * NPART + idx)) * NQ + (r0 + r)] = v[0] * rinv;
        }
    }
}

// ---------------------------------------------------------------------------
// 5) pred_logits[b,c] = sum_n logits[b,n,c*12+n]
// ---------------------------------------------------------------------------
__global__ void pred_kernel(float* __restrict__ out) {
    int t = blockIdx.x * blockDim.x + threadIdx.x;   // 0..25599
    if (t >= Bsz * NCLS) return;
    int b = t / NCLS, c = t % NCLS;
    float s = 0.0f;
#pragma unroll
    for (int n = 0; n < NPART; ++n)
        s += out[((size_t)(b * NPART + n)) * NQ + c * NPART + n];
    out[LOGITS_ELEMS + t] = s;
}

// ---------------------------------------------------------------------------
extern "C" void kernel_launch(void* const* d_in, const int* in_sizes, int n_in,
                              void* d_out, int out_size) {
    const float* image = (const float*)d_in[0];
    const float* query = (const float*)d_in[1];
    const int* topk = (const int*)d_in[2];
    const float* W1 = (const float*)d_in[3];
    const float* b1 = (const float*)d_in[4];
    const float* W2 = (const float*)d_in[5];
    const float* b2 = (const float*)d_in[6];
    const float* W3 = (const float*)d_in[7];
    const float* b3 = (const float*)d_in[8];
    float* out = (float*)d_out;

    float* parts; float* h1; float* h2; float* img;
    cudaGetSymbolAddress((void**)&parts, g_parts);
    cudaGetSymbolAddress((void**)&h1, g_h1);
    cudaGetSymbolAddress((void**)&h2, g_h2);
    cudaGetSymbolAddress((void**)&img, g_img);

    gather_kernel<<<MROWS, 192>>>(image, topk);
    gemm_bias_gelu<<<dim3(MROWS / GBM, DV / GBN), 256>>>(parts, W1, b1, h1, DV);
    gemm_bias_gelu<<<dim3(MROWS / GBM, DV / GBN), 256>>>(h1, W2, b2, h2, DV);
    gemm_bias_gelu<<<dim3(MROWS / GBM, DT / GBN), 256>>>(h2, W3, b3, img, DT);
    l2norm_kernel<<<MROWS, 128>>>();
    logits_kernel<<<dim3(NQ / 96, Bsz), 256>>>(query, out);
    pred_kernel<<<(Bsz * NCLS + 255) / 256, 256>>>(out);
}

// round 5
// speedup vs baseline: 1.5596x; 1.0621x over previous
#include <cuda_runtime.h>
#include <math.h>

// ---------------------------------------------------------------------------
// OwlViT prediction head
//   B=32, P=576, DV=768, DT=512, N_PARTS=12, K=3, NUM_CLASSES=800
//   out = [logits_reshaped (384*9600) | pred_logits (32*800)] fp32
// ---------------------------------------------------------------------------

#define Bsz 32
#define Pn 576
#define DV 768
#define DT 512
#define NPART 12
#define TOPK 3
#define NCLS 800
#define NQ (NCLS * NPART)      // 9600 query rows per batch
#define MROWS (Bsz * NPART)    // 384
#define LOGITS_ELEMS ((size_t)MROWS * NQ)

// scratch (static device memory; no allocations allowed)
__device__ float g_h1[MROWS * DV];
__device__ float g_h2[MROWS * DV];
__device__ float g_img[MROWS * DT];

// ---------------------------------------------------------------------------
__device__ __forceinline__ void fma2(unsigned long long& d,
                                     unsigned long long a,
                                     unsigned long long b) {
    asm("fma.rn.f32x2 %0, %1, %2, %0;" : "+l"(d) : "l"(a), "l"(b));
}

__device__ __forceinline__ float pair_sum(unsigned long long v) {
    float lo = __uint_as_float((unsigned)(v & 0xffffffffull));
    float hi = __uint_as_float((unsigned)(v >> 32));
    return lo + hi;
}

__device__ __forceinline__ float gelu_exact(float x) {
    return 0.5f * x * (1.0f + erff(x * 0.70710678118654752f));
}

// ---------------------------------------------------------------------------
// GEMM: C[M,N] = gelu(A[M,768] * W[N,768]^T + bias), smem double-buffered.
// BM=32 BN=64 BK=32, 256 threads, 2x4 outputs/thread, f32x2 k-pair FMAs.
// GATHER=true: A row r is the dedup-sum of topk image rows (fused gather).
// ---------------------------------------------------------------------------
#define GBM 32
#define GBN 64
#define GBK 32
#define GPAD 36
#define NITER (DV / GBK)   // 24

template<bool GATHER>
__global__ void __launch_bounds__(256)
gemm_kernel(const float* __restrict__ A, const float* __restrict__ W,
            const float* __restrict__ bias, float* __restrict__ C, int N,
            const int* __restrict__ idx) {
    __shared__ __align__(16) float As[2][GBM][GPAD];
    __shared__ __align__(16) float Ws[2][GBN][GPAD];
    int t = threadIdx.x;
    int tx = t & 15;                 // cols tx + 16j
    int ty = t >> 4;                 // rows ty*2 + i
    int bm = blockIdx.x * GBM, bn = blockIdx.y * GBN;

    int ar = t >> 3, ak = (t & 7) * 4;    // A tile: 1 float4/thread
    int wr = t >> 2, wk = (t & 3) * 8;    // W tile: 2 float4/thread

    const float *Arow0, *Arow1, *Arow2;
    bool u1 = false, u2 = false;
    if (GATHER) {
        int row = bm + ar;
        int bb = row / NPART, n = row - bb * NPART;
        int i0 = idx[(bb * TOPK + 0) * NPART + n];
        int i1 = idx[(bb * TOPK + 1) * NPART + n];
        int i2 = idx[(bb * TOPK + 2) * NPART + n];
        i0 = min(max(i0, 0), Pn - 1);
        i1 = min(max(i1, 0), Pn - 1);
        i2 = min(max(i2, 0), Pn - 1);
        u1 = (i1 != i0);
        u2 = (i2 != i0) && (i2 != i1);
        const float* base = A + (size_t)bb * Pn * DV;
        Arow0 = base + (size_t)i0 * DV;
        Arow1 = base + (size_t)i1 * DV;
        Arow2 = base + (size_t)i2 * DV;
    } else {
        Arow0 = A + (size_t)(bm + ar) * DV;
        Arow1 = Arow0; Arow2 = Arow0;
    }
    const float* Wg = W + (size_t)(bn + wr) * DV;

    auto loadA = [&](int k0) -> float4 {
        float4 s = *(const float4*)(Arow0 + k0 + ak);
        if (GATHER) {
            if (u1) { float4 v = *(const float4*)(Arow1 + k0 + ak);
                      s.x += v.x; s.y += v.y; s.z += v.z; s.w += v.w; }
            if (u2) { float4 v = *(const float4*)(Arow2 + k0 + ak);
                      s.x += v.x; s.y += v.y; s.z += v.z; s.w += v.w; }
        }
        return s;
    };

    unsigned long long acc2[2][4];
#pragma unroll
    for (int i = 0; i < 2; ++i)
#pragma unroll
        for (int j = 0; j < 4; ++j) acc2[i][j] = 0ull;

    // prologue: tile0 -> smem[0]; tile1 -> regs
    float4 a_r = loadA(0);
    float4 w_r0 = *(const float4*)(Wg + wk);
    float4 w_r1 = *(const float4*)(Wg + wk + 4);
    *(float4*)&As[0][ar][ak] = a_r;
    *(float4*)&Ws[0][wr][wk] = w_r0;
    *(float4*)&Ws[0][wr][wk + 4] = w_r1;
    a_r  = loadA(GBK);
    w_r0 = *(const float4*)(Wg + GBK + wk);
    w_r1 = *(const float4*)(Wg + GBK + wk + 4);
    __syncthreads();

#pragma unroll 1
    for (int i = 0; i < NITER; ++i) {
        int buf = i & 1, nbuf = buf ^ 1;
        if (i + 1 < NITER) {
            *(float4*)&As[nbuf][ar][ak] = a_r;
            *(float4*)&Ws[nbuf][wr][wk] = w_r0;
            *(float4*)&Ws[nbuf][wr][wk + 4] = w_r1;
        }
        if (i + 2 < NITER) {
            int k0 = (i + 2) * GBK;
            a_r  = loadA(k0);
            w_r0 = *(const float4*)(Wg + k0 + wk);
            w_r1 = *(const float4*)(Wg + k0 + wk + 4);
        }
#pragma unroll
        for (int kk = 0; kk < GBK; kk += 4) {
            ulonglong2 ap[2], wp[4];
            ap[0] = *(const ulonglong2*)&As[buf][ty * 2][kk];
            ap[1] = *(const ulonglong2*)&As[buf][ty * 2 + 1][kk];
#pragma unroll
            for (int j = 0; j < 4; ++j)
                wp[j] = *(const ulonglong2*)&Ws[buf][tx + 16 * j][kk];
#pragma unroll
            for (int ii = 0; ii < 2; ++ii)
#pragma unroll
                for (int j = 0; j < 4; ++j) {
                    fma2(acc2[ii][j], ap[ii].x, wp[j].x);
                    fma2(acc2[ii][j], ap[ii].y, wp[j].y);
                }
        }
        __syncthreads();
    }

#pragma unroll
    for (int i = 0; i < 2; ++i) {
        int row = bm + ty * 2 + i;
#pragma unroll
        for (int j = 0; j < 4; ++j) {
            int col = bn + tx + 16 * j;
            float x = pair_sum(acc2[i][j]) + bias[col];
            C[(size_t)row * N + col] = gelu_exact(x);
        }
    }
}

// ---------------------------------------------------------------------------
// logits[b,n,i] = dot(img_n[b,n], q[b,i]) / max(||q[b,i]||, eps)
// 256 threads (8 warps), 2 q-rows/warp, 6 passes -> 96 rows/block.
// img normalized in-kernel (l2norm fused). Output staged via shared ->
// coalesced 384B global write runs.
// ---------------------------------------------------------------------------
__global__ void __launch_bounds__(256, 2)
logits_kernel(const float* __restrict__ q, float* __restrict__ out) {
    __shared__ __align__(16) float img_s[NPART * DT];      // 24 KB
    __shared__ float logit_s[NPART][97];                    // pad 97: no conflicts
    int b = blockIdx.y;
    int warp = threadIdx.x >> 5;
    int lane = threadIdx.x & 31;

    {   // stage (unnormalized) img tile for this batch
        const float4* src = (const float4*)(g_img + (size_t)b * NPART * DT);
        float4* dst = (float4*)img_s;
#pragma unroll
        for (int i = 0; i < 6; ++i)
            dst[threadIdx.x + i * 256] = src[threadIdx.x + i * 256];
    }
    __syncthreads();

    // fused l2 normalization of the 12 img rows
    for (int row = warp; row < NPART; row += 8) {
        float* rp = img_s + row * DT;
        float4 v0 = *(float4*)(rp + lane * 4);
        float4 v1 = *(float4*)(rp + lane * 4 + 128);
        float4 v2 = *(float4*)(rp + lane * 4 + 256);
        float4 v3 = *(float4*)(rp + lane * 4 + 384);
        float ss = v0.x*v0.x + v0.y*v0.y + v0.z*v0.z + v0.w*v0.w
                 + v1.x*v1.x + v1.y*v1.y + v1.z*v1.z + v1.w*v1.w
                 + v2.x*v2.x + v2.y*v2.y + v2.z*v2.z + v2.w*v2.w
                 + v3.x*v3.x + v3.y*v3.y + v3.z*v3.z + v3.w*v3.w;
#pragma unroll
        for (int off = 16; off > 0; off >>= 1)
            ss += __shfl_xor_sync(0xffffffffu, ss, off);
        float rinv = 1.0f / fmaxf(sqrtf(ss), 1e-12f);
        v0.x*=rinv; v0.y*=rinv; v0.z*=rinv; v0.w*=rinv;
        v1.x*=rinv; v1.y*=rinv; v1.z*=rinv; v1.w*=rinv;
        v2.x*=rinv; v2.y*=rinv; v2.z*=rinv; v2.w*=rinv;
        v3.x*=rinv; v3.y*=rinv; v3.z*=rinv; v3.w*=rinv;
        *(float4*)(rp + lane * 4)       = v0;
        *(float4*)(rp + lane * 4 + 128) = v1;
        *(float4*)(rp + lane * 4 + 256) = v2;
        *(float4*)(rp + lane * 4 + 384) = v3;
    }
    __syncthreads();

    const float* qb = q + (size_t)b * NQ * DT;
    int rowbase = blockIdx.x * 96 + warp * 2;

#pragma unroll 1
    for (int p = 0; p < 6; ++p) {
        int r0 = rowbase + p * 16;

        // batched global loads: 2 rows x 4 x LDG.128 (MLP depth 8)
        ulonglong2 qv[2][4];
#pragma unroll
        for (int r = 0; r < 2; ++r) {
            const float* qr = qb + (size_t)(r0 + r) * DT + lane * 4;
#pragma unroll
            for (int it = 0; it < 4; ++it)
                qv[r][it] = *(const ulonglong2*)(qr + it * 128);
        }

        unsigned long long acc[2][13];
#pragma unroll
        for (int r = 0; r < 2; ++r)
#pragma unroll
            for (int j = 0; j < 13; ++j) acc[r][j] = 0ull;

#pragma unroll
        for (int it = 0; it < 4; ++it) {
            int k = it * 128 + lane * 4;
#pragma unroll
            for (int n = 0; n < NPART; ++n) {
                ulonglong2 im = *(const ulonglong2*)&img_s[n * DT + k];
                fma2(acc[0][n], qv[0][it].x, im.x);
                fma2(acc[0][n], qv[0][it].y, im.y);
                fma2(acc[1][n], qv[1][it].x, im.x);
                fma2(acc[1][n], qv[1][it].y, im.y);
            }
            fma2(acc[0][12], qv[0][it].x, qv[0][it].x);
            fma2(acc[0][12], qv[0][it].y, qv[0][it].y);
            fma2(acc[1][12], qv[1][it].x, qv[1][it].x);
            fma2(acc[1][12], qv[1][it].y, qv[1][it].y);
        }

#pragma unroll
        for (int r = 0; r < 2; ++r) {
            float v[16];
#pragma unroll
            for (int j = 0; j < 13; ++j) v[j] = pair_sum(acc[r][j]);
            v[13] = 0.0f; v[14] = 0.0f; v[15] = 0.0f;

            // halving tree: lanes {2j,2j+1} end with value j=(lane>>1)&15
#pragma unroll
            for (int d = 16; d >= 2; d >>= 1) {
#pragma unroll
                for (int j = 0; j < d / 2; ++j) {
                    float send = (lane & d) ? v[j] : v[j + d / 2];
                    float recv = __shfl_xor_sync(0xffffffffu, send, d);
                    v[j] = (lane & d) ? (v[j + d / 2] + recv) : (v[j] + recv);
                }
            }
            v[0] += __shfl_xor_sync(0xffffffffu, v[0], 1);

            int idxv = (lane >> 1) & 15;
            float nq = __shfl_sync(0xffffffffu, v[0], 24);   // value 12 = |q|^2
            float rinv = 1.0f / fmaxf(sqrtf(nq), 1e-12f);
            int lr = warp * 2 + p * 16 + r;                  // 0..95
            if (((lane & 1) == 0) && idxv < NPART)
                logit_s[idxv][lr] = v[0] * rinv;
        }
    }
    __syncthreads();

    // coalesced write-out: 12 runs of 96 consecutive floats
    {
        int base_i = blockIdx.x * 96;
#pragma unroll
        for (int u = threadIdx.x; u < NPART * 96; u += 256) {
            int n = u / 96, c = u - n * 96;
            out[((size_t)(b * NPART + n)) * NQ + base_i + c] = logit_s[n][c];
        }
    }
}

// ---------------------------------------------------------------------------
// pred_logits[b,c] = sum_n logits[b,n,c*12+n]
// ---------------------------------------------------------------------------
__global__ void pred_kernel(float* __restrict__ out) {
    int t = blockIdx.x * blockDim.x + threadIdx.x;   // 0..25599
    if (t >= Bsz * NCLS) return;
    int b = t / NCLS, c = t % NCLS;
    float s = 0.0f;
#pragma unroll
    for (int n = 0; n < NPART; ++n)
        s += out[((size_t)(b * NPART + n)) * NQ + c * NPART + n];
    out[LOGITS_ELEMS + t] = s;
}

// ---------------------------------------------------------------------------
extern "C" void kernel_launch(void* const* d_in, const int* in_sizes, int n_in,
                              void* d_out, int out_size) {
    const float* image = (const float*)d_in[0];
    const float* query = (const float*)d_in[1];
    const int* topk = (const int*)d_in[2];
    const float* W1 = (const float*)d_in[3];
    const float* b1 = (const float*)d_in[4];
    const float* W2 = (const float*)d_in[5];
    const float* b2 = (const float*)d_in[6];
    const float* W3 = (const float*)d_in[7];
    const float* b3 = (const float*)d_in[8];
    float* out = (float*)d_out;

    float* h1; float* h2; float* img;
    cudaGetSymbolAddress((void**)&h1, g_h1);
    cudaGetSymbolAddress((void**)&h2, g_h2);
    cudaGetSymbolAddress((void**)&img, g_img);

    // launch order keeps logits at global index 5 (2 harness preamble
    // launches + 3 here) so ncu -s 5 -c 1 captures it.
    gemm_kernel<true ><<<dim3(MROWS / GBM, DV / GBN), 256>>>(image, W1, b1, h1, DV, topk);
    gemm_kernel<false><<<dim3(MROWS / GBM, DV / GBN), 256>>>(h1, W2, b2, h2, DV, nullptr);
    gemm_kernel<false><<<dim3(MROWS / GBM, DT / GBN), 256>>>(h2, W3, b3, img, DT, nullptr);
    logits_kernel<<<dim3(NQ / 96, Bsz), 256>>>(query, out);
    pred_kernel<<<(Bsz * NCLS + 255) / 256, 256>>>(out);
}

// round 6
// speedup vs baseline: 2.8472x; 1.8256x over previous
#include <cuda_runtime.h>
#include <math.h>

// ---------------------------------------------------------------------------
// OwlViT prediction head
//   B=32, P=576, DV=768, DT=512, N_PARTS=12, K=3, NUM_CLASSES=800
//   out = [logits_reshaped (384*9600) | pred_logits (32*800)] fp32
// ---------------------------------------------------------------------------

#define Bsz 32
#define Pn 576
#define DV 768
#define DT 512
#define NPART 12
#define TOPK 3
#define NCLS 800
#define NQ (NCLS * NPART)      // 9600 query rows per batch
#define MROWS (Bsz * NPART)    // 384
#define LOGITS_ELEMS ((size_t)MROWS * NQ)

// scratch (static device memory; no allocations allowed)
__device__ float g_h1[MROWS * DV];
__device__ float g_h2[MROWS * DV];
__device__ float g_img[MROWS * DT];

// ---------------------------------------------------------------------------
__device__ __forceinline__ void fma2(unsigned long long& d,
                                     unsigned long long a,
                                     unsigned long long b) {
    asm("fma.rn.f32x2 %0, %1, %2, %0;" : "+l"(d) : "l"(a), "l"(b));
}

__device__ __forceinline__ float pair_sum(unsigned long long v) {
    float lo = __uint_as_float((unsigned)(v & 0xffffffffull));
    float hi = __uint_as_float((unsigned)(v >> 32));
    return lo + hi;
}

__device__ __forceinline__ float gelu_exact(float x) {
    return 0.5f * x * (1.0f + erff(x * 0.70710678118654752f));
}

// ---------------------------------------------------------------------------
// GEMM: C[M,N] = gelu(A[M,768] * W[N,768]^T + bias), smem double-buffered.
// BM=32 BN=64 BK=32, 256 threads, 2x4 outputs/thread, f32x2 k-pair FMAs.
// GATHER=true: A row r is the dedup-sum of topk image rows (fused gather).
// ---------------------------------------------------------------------------
#define GBM 32
#define GBN 64
#define GBK 32
#define GPAD 36
#define NITER (DV / GBK)   // 24

template<bool GATHER>
__global__ void __launch_bounds__(256)
gemm_kernel(const float* __restrict__ A, const float* __restrict__ W,
            const float* __restrict__ bias, float* __restrict__ C, int N,
            const int* __restrict__ idx) {
    __shared__ __align__(16) float As[2][GBM][GPAD];
    __shared__ __align__(16) float Ws[2][GBN][GPAD];
    int t = threadIdx.x;
    int tx = t & 15;                 // cols tx + 16j
    int ty = t >> 4;                 // rows ty*2 + i
    int bm = blockIdx.x * GBM, bn = blockIdx.y * GBN;

    int ar = t >> 3, ak = (t & 7) * 4;    // A tile: 1 float4/thread
    int wr = t >> 2, wk = (t & 3) * 8;    // W tile: 2 float4/thread

    const float *Arow0, *Arow1, *Arow2;
    bool u1 = false, u2 = false;
    if (GATHER) {
        int row = bm + ar;
        int bb = row / NPART, n = row - bb * NPART;
        int i0 = idx[(bb * TOPK + 0) * NPART + n];
        int i1 = idx[(bb * TOPK + 1) * NPART + n];
        int i2 = idx[(bb * TOPK + 2) * NPART + n];
        i0 = min(max(i0, 0), Pn - 1);
        i1 = min(max(i1, 0), Pn - 1);
        i2 = min(max(i2, 0), Pn - 1);
        u1 = (i1 != i0);
        u2 = (i2 != i0) && (i2 != i1);
        const float* base = A + (size_t)bb * Pn * DV;
        Arow0 = base + (size_t)i0 * DV;
        Arow1 = base + (size_t)i1 * DV;
        Arow2 = base + (size_t)i2 * DV;
    } else {
        Arow0 = A + (size_t)(bm + ar) * DV;
        Arow1 = Arow0; Arow2 = Arow0;
    }
    const float* Wg = W + (size_t)(bn + wr) * DV;

    auto loadA = [&](int k0) -> float4 {
        float4 s = *(const float4*)(Arow0 + k0 + ak);
        if (GATHER) {
            if (u1) { float4 v = *(const float4*)(Arow1 + k0 + ak);
                      s.x += v.x; s.y += v.y; s.z += v.z; s.w += v.w; }
            if (u2) { float4 v = *(const float4*)(Arow2 + k0 + ak);
                      s.x += v.x; s.y += v.y; s.z += v.z; s.w += v.w; }
        }
        return s;
    };

    unsigned long long acc2[2][4];
#pragma unroll
    for (int i = 0; i < 2; ++i)
#pragma unroll
        for (int j = 0; j < 4; ++j) acc2[i][j] = 0ull;

    // prologue: tile0 -> smem[0]; tile1 -> regs
    float4 a_r = loadA(0);
    float4 w_r0 = *(const float4*)(Wg + wk);
    float4 w_r1 = *(const float4*)(Wg + wk + 4);
    *(float4*)&As[0][ar][ak] = a_r;
    *(float4*)&Ws[0][wr][wk] = w_r0;
    *(float4*)&Ws[0][wr][wk + 4] = w_r1;
    a_r  = loadA(GBK);
    w_r0 = *(const float4*)(Wg + GBK + wk);
    w_r1 = *(const float4*)(Wg + GBK + wk + 4);
    __syncthreads();

#pragma unroll 1
    for (int i = 0; i < NITER; ++i) {
        int buf = i & 1, nbuf = buf ^ 1;
        if (i + 1 < NITER) {
            *(float4*)&As[nbuf][ar][ak] = a_r;
            *(float4*)&Ws[nbuf][wr][wk] = w_r0;
            *(float4*)&Ws[nbuf][wr][wk + 4] = w_r1;
        }
        if (i + 2 < NITER) {
            int k0 = (i + 2) * GBK;
            a_r  = loadA(k0);
            w_r0 = *(const float4*)(Wg + k0 + wk);
            w_r1 = *(const float4*)(Wg + k0 + wk + 4);
        }
#pragma unroll
        for (int kk = 0; kk < GBK; kk += 4) {
            ulonglong2 ap[2], wp[4];
            ap[0] = *(const ulonglong2*)&As[buf][ty * 2][kk];
            ap[1] = *(const ulonglong2*)&As[buf][ty * 2 + 1][kk];
#pragma unroll
            for (int j = 0; j < 4; ++j)
                wp[j] = *(const ulonglong2*)&Ws[buf][tx + 16 * j][kk];
#pragma unroll
            for (int ii = 0; ii < 2; ++ii)
#pragma unroll
                for (int j = 0; j < 4; ++j) {
                    fma2(acc2[ii][j], ap[ii].x, wp[j].x);
                    fma2(acc2[ii][j], ap[ii].y, wp[j].y);
                }
        }
        __syncthreads();
    }

#pragma unroll
    for (int i = 0; i < 2; ++i) {
        int row = bm + ty * 2 + i;
#pragma unroll
        for (int j = 0; j < 4; ++j) {
            int col = bn + tx + 16 * j;
            float x = pair_sum(acc2[i][j]) + bias[col];
            C[(size_t)row * N + col] = gelu_exact(x);
        }
    }
}

// ---------------------------------------------------------------------------
// logits: lane-owns-row formulation.
// Block = 128 threads; thread t owns q-row blockIdx.x*128 + t of batch
// blockIdx.y. q tiles (128 rows x 16 k) staged via shared, coalesced LDG,
// XOR-swizzled STS/LDS (conflict-free). img reads are warp-uniform
// broadcasts. 13 f32x2 accumulators/thread; no reduction, coalesced STG.
// smem: img 24KB + q 2x8KB = 40KB static.
// ---------------------------------------------------------------------------
#define QTILE 16
#define NTILE (DT / QTILE)   // 32

__global__ void __launch_bounds__(128)
logits_kernel(const float* __restrict__ q, float* __restrict__ out) {
    __shared__ __align__(16) float img_s[NPART * DT];     // 24 KB
    __shared__ __align__(16) float q_s[2][128 * QTILE];   // 16 KB
    int t = threadIdx.x;
    int warp = t >> 5, lane = t & 31;
    int b = blockIdx.y;

    {   // stage img tile for this batch (1536 float4, 12/thread)
        const float4* src = (const float4*)(g_img + (size_t)b * NPART * DT);
        float4* dst = (float4*)img_s;
#pragma unroll
        for (int i = 0; i < 12; ++i)
            dst[t + i * 128] = src[t + i * 128];
    }
    __syncthreads();

    // fused l2 normalization of the 12 img rows (4 warps, 3 rows each)
    for (int row = warp; row < NPART; row += 4) {
        float* rp = img_s + row * DT;
        float4 v0 = *(float4*)(rp + lane * 4);
        float4 v1 = *(float4*)(rp + lane * 4 + 128);
        float4 v2 = *(float4*)(rp + lane * 4 + 256);
        float4 v3 = *(float4*)(rp + lane * 4 + 384);
        float ss = v0.x*v0.x + v0.y*v0.y + v0.z*v0.z + v0.w*v0.w
                 + v1.x*v1.x + v1.y*v1.y + v1.z*v1.z + v1.w*v1.w
                 + v2.x*v2.x + v2.y*v2.y + v2.z*v2.z + v2.w*v2.w
                 + v3.x*v3.x + v3.y*v3.y + v3.z*v3.z + v3.w*v3.w;
#pragma unroll
        for (int off = 16; off > 0; off >>= 1)
            ss += __shfl_xor_sync(0xffffffffu, ss, off);
        float rinv = 1.0f / fmaxf(sqrtf(ss), 1e-12f);
        v0.x*=rinv; v0.y*=rinv; v0.z*=rinv; v0.w*=rinv;
        v1.x*=rinv; v1.y*=rinv; v1.z*=rinv; v1.w*=rinv;
        v2.x*=rinv; v2.y*=rinv; v2.z*=rinv; v2.w*=rinv;
        v3.x*=rinv; v3.y*=rinv; v3.z*=rinv; v3.w*=rinv;
        *(float4*)(rp + lane * 4)       = v0;
        *(float4*)(rp + lane * 4 + 128) = v1;
        *(float4*)(rp + lane * 4 + 256) = v2;
        *(float4*)(rp + lane * 4 + 384) = v3;
    }

    const float* qb = q + (size_t)b * NQ * DT + (size_t)(blockIdx.x * 128) * DT;
    int sw = (t ^ (t >> 2)) & 3;   // lane's LDS swizzle (row = t)

    // prologue: tile 0 -> regs -> smem buf0
    float4 pf[4];
#pragma unroll
    for (int j = 0; j < 4; ++j) {
        int idx = j * 128 + t, row = idx >> 2, slot = idx & 3;
        pf[j] = *(const float4*)(qb + (size_t)row * DT + slot * 4);
    }
#pragma unroll
    for (int j = 0; j < 4; ++j) {
        int idx = j * 128 + t, row = idx >> 2, slot = idx & 3;
        int sl = slot ^ ((row ^ (row >> 2)) & 3);
        *(float4*)&q_s[0][row * QTILE + sl * 4] = pf[j];
    }
    __syncthreads();

    unsigned long long acc[13];
#pragma unroll
    for (int j = 0; j < 13; ++j) acc[j] = 0ull;

#pragma unroll 1
    for (int tile = 0; tile < NTILE; ++tile) {
        int buf = tile & 1;
        if (tile + 1 < NTILE) {
            int k0 = (tile + 1) * QTILE;
#pragma unroll
            for (int j = 0; j < 4; ++j) {
                int idx = j * 128 + t, row = idx >> 2, slot = idx & 3;
                pf[j] = *(const float4*)(qb + (size_t)row * DT + k0 + slot * 4);
            }
        }
#pragma unroll
        for (int j = 0; j < 4; ++j) {
            ulonglong2 qp = *(const ulonglong2*)&q_s[buf][t * QTILE + ((j ^ sw) << 2)];
            int k = tile * QTILE + j * 4;
#pragma unroll
            for (int n = 0; n < NPART; ++n) {
                ulonglong2 ip = *(const ulonglong2*)&img_s[n * DT + k];
                fma2(acc[n], qp.x, ip.x);
                fma2(acc[n], qp.y, ip.y);
            }
            fma2(acc[12], qp.x, qp.x);
            fma2(acc[12], qp.y, qp.y);
        }
        if (tile + 1 < NTILE) {
#pragma unroll
            for (int j = 0; j < 4; ++j) {
                int idx = j * 128 + t, row = idx >> 2, slot = idx & 3;
                int sl = slot ^ ((row ^ (row >> 2)) & 3);
                *(float4*)&q_s[buf ^ 1][row * QTILE + sl * 4] = pf[j];
            }
        }
        __syncthreads();
    }

    float s[13];
#pragma unroll
    for (int j = 0; j < 13; ++j) s[j] = pair_sum(acc[j]);
    float rinv = 1.0f / fmaxf(sqrtf(s[12]), 1e-12f);
    int r = blockIdx.x * 128 + t;
#pragma unroll
    for (int n = 0; n < NPART; ++n)
        out[((size_t)(b * NPART + n)) * NQ + r] = s[n] * rinv;
}

// ---------------------------------------------------------------------------
// pred_logits[b,c] = sum_n logits[b,n,c*12+n]
// ---------------------------------------------------------------------------
__global__ void pred_kernel(float* __restrict__ out) {
    int t = blockIdx.x * blockDim.x + threadIdx.x;   // 0..25599
    if (t >= Bsz * NCLS) return;
    int b = t / NCLS, c = t % NCLS;
    float s = 0.0f;
#pragma unroll
    for (int n = 0; n < NPART; ++n)
        s += out[((size_t)(b * NPART + n)) * NQ + c * NPART + n];
    out[LOGITS_ELEMS + t] = s;
}

// ---------------------------------------------------------------------------
extern "C" void kernel_launch(void* const* d_in, const int* in_sizes, int n_in,
                              void* d_out, int out_size) {
    const float* image = (const float*)d_in[0];
    const float* query = (const float*)d_in[1];
    const int* topk = (const int*)d_in[2];
    const float* W1 = (const float*)d_in[3];
    const float* b1 = (const float*)d_in[4];
    const float* W2 = (const float*)d_in[5];
    const float* b2 = (const float*)d_in[6];
    const float* W3 = (const float*)d_in[7];
    const float* b3 = (const float*)d_in[8];
    float* out = (float*)d_out;

    float* h1; float* h2; float* img;
    cudaGetSymbolAddress((void**)&h1, g_h1);
    cudaGetSymbolAddress((void**)&h2, g_h2);
    cudaGetSymbolAddress((void**)&img, g_img);

    // launch order keeps logits at global index 5 (2 harness preamble
    // launches + 3 here) so ncu -s 5 -c 1 captures it.
    gemm_kernel<true ><<<dim3(MROWS / GBM, DV / GBN), 256>>>(image, W1, b1, h1, DV, topk);
    gemm_kernel<false><<<dim3(MROWS / GBM, DV / GBN), 256>>>(h1, W2, b2, h2, DV, nullptr);
    gemm_kernel<false><<<dim3(MROWS / GBM, DT / GBN), 256>>>(h2, W3, b3, img, DT, nullptr);
    logits_kernel<<<dim3(NQ / 128, Bsz), 128>>>(query, out);
    pred_kernel<<<(Bsz * NCLS + 255) / 256, 256>>>(out);
}